// round 1
// baseline (speedup 1.0000x reference)
#include <cuda_runtime.h>

#define BB 32
#define CC_ 32
#define HH 128
#define WW 128
#define FF 64
#define ORR 64
#define OCC 64

// Tile: 1 pooled row (2 input rows) x 8 pooled cols (16 input cols), full B x F.
// Block: 512 threads. tid -> g = tid>>6 (pooled col within tile, 0..7),
// r = tid&63, bsub = r&7 (b-subtile of 4), fsub = r>>3 (f-subtile of 8).
// Each thread: acc[4][8] over b = bsub*4+bi, f = fsub*8+fj, one pooled group.
// Channels staged 2-at-a-time through smem with register prefetch.

__global__ __launch_bounds__(512, 1)
void lc2d_kernel(const float* __restrict__ x,
                 const float* __restrict__ w,
                 const float* __restrict__ bias,
                 float* __restrict__ out) {
    __shared__ float xs[2][32][36];  // [c][px][b]  (pad 36 to break transpose-store conflicts)
    __shared__ float ws[2][32][68];  // [c][px][f]  (pad 68)

    const int tid  = threadIdx.x;
    const int or_  = blockIdx.y;            // pooled row
    const int oct0 = blockIdx.x * 8;        // pooled col base of tile
    const int h0   = or_ * 2;
    const int w0   = oct0 * 2;

    // compute-side mapping
    const int g    = tid >> 6;
    const int r    = tid & 63;
    const int bsub = r & 7;
    const int fsub = r >> 3;

    // loader-side mapping
    const int xcol = tid & 15;              // 0..15 input col
    const int xb   = (tid >> 4) & 31;       // 0..31 batch
    const int wsv  = tid & 7;               // col pair (2 floats)
    const int wf   = tid >> 3;              // 0..63 filter

    float acc[4][8];
#pragma unroll
    for (int i = 0; i < 4; ++i)
#pragma unroll
        for (int j = 0; j < 8; ++j) acc[i][j] = 0.f;

    float px_[4];   // prefetch regs for x: [cc*2+rr]
    float pw_[8];   // prefetch regs for W: [cc*4 + rr*2 + {0,1}]

    // ---- prefetch c0 = 0 ----
#pragma unroll
    for (int cc = 0; cc < 2; ++cc)
#pragma unroll
        for (int rr = 0; rr < 2; ++rr) {
            px_[cc * 2 + rr] =
                x[(((size_t)xb * CC_ + cc) * HH + (h0 + rr)) * WW + w0 + xcol];
            const float2 v = *reinterpret_cast<const float2*>(
                &w[(((size_t)wf * CC_ + cc) * HH + (h0 + rr)) * WW + w0 + 2 * wsv]);
            pw_[cc * 4 + rr * 2 + 0] = v.x;
            pw_[cc * 4 + rr * 2 + 1] = v.y;
        }

    for (int c0 = 0; c0 < CC_; c0 += 2) {
        // ---- stage prefetched regs into smem ----
#pragma unroll
        for (int cc = 0; cc < 2; ++cc)
#pragma unroll
            for (int rr = 0; rr < 2; ++rr) {
                xs[cc][rr * 16 + xcol][xb] = px_[cc * 2 + rr];
                ws[cc][rr * 16 + 2 * wsv + 0][wf] = pw_[cc * 4 + rr * 2 + 0];
                ws[cc][rr * 16 + 2 * wsv + 1][wf] = pw_[cc * 4 + rr * 2 + 1];
            }
        __syncthreads();

        // ---- prefetch next stage (overlaps with compute below) ----
        if (c0 + 2 < CC_) {
            const int cn = c0 + 2;
#pragma unroll
            for (int cc = 0; cc < 2; ++cc)
#pragma unroll
                for (int rr = 0; rr < 2; ++rr) {
                    px_[cc * 2 + rr] =
                        x[(((size_t)xb * CC_ + (cn + cc)) * HH + (h0 + rr)) * WW + w0 + xcol];
                    const float2 v = *reinterpret_cast<const float2*>(
                        &w[(((size_t)wf * CC_ + (cn + cc)) * HH + (h0 + rr)) * WW + w0 + 2 * wsv]);
                    pw_[cc * 4 + rr * 2 + 0] = v.x;
                    pw_[cc * 4 + rr * 2 + 1] = v.y;
                }
        }

        // ---- compute: 2 channels x 4 pixels of this thread's pooled group ----
#pragma unroll
        for (int cc = 0; cc < 2; ++cc) {
#pragma unroll
            for (int pp = 0; pp < 4; ++pp) {
                const int px = 2 * g + (pp & 1) + ((pp >> 1) ? 16 : 0);
                const float4 xa = *reinterpret_cast<const float4*>(&xs[cc][px][bsub * 4]);
                const float4 wa = *reinterpret_cast<const float4*>(&ws[cc][px][fsub * 8]);
                const float4 wb = *reinterpret_cast<const float4*>(&ws[cc][px][fsub * 8 + 4]);
                const float xv[4] = {xa.x, xa.y, xa.z, xa.w};
                const float wv[8] = {wa.x, wa.y, wa.z, wa.w, wb.x, wb.y, wb.z, wb.w};
#pragma unroll
                for (int bi = 0; bi < 4; ++bi)
#pragma unroll
                    for (int fj = 0; fj < 8; ++fj)
                        acc[bi][fj] = fmaf(xv[bi], wv[fj], acc[bi][fj]);
            }
        }
        __syncthreads();
    }

    // ---- epilogue: bias (raw keras reshape) + relu + store ----
    const int oc = oct0 + g;
#pragma unroll
    for (int bi = 0; bi < 4; ++bi) {
        const int b_ = bsub * 4 + bi;
#pragma unroll
        for (int fj = 0; fj < 8; ++fj) {
            const int f_ = fsub * 8 + fj;
            const float bv = bias[(size_t)f_ * ORR * OCC + or_ * OCC + oc];
            const float v  = acc[bi][fj] + bv;
            out[(((size_t)b_ * FF + f_) * ORR + or_) * OCC + oc] = fmaxf(v, 0.f);
        }
    }
}

extern "C" void kernel_launch(void* const* d_in, const int* in_sizes, int n_in,
                              void* d_out, int out_size) {
    const float* x    = (const float*)d_in[0];
    const float* w    = (const float*)d_in[1];
    const float* bias = (const float*)d_in[2];
    float* out        = (float*)d_out;
    dim3 grid(OCC / 8, ORR, 1);
    lc2d_kernel<<<grid, 512>>>(x, w, bias, out);
}

// round 2
// speedup vs baseline: 1.2221x; 1.2221x over previous
#include <cuda_runtime.h>

#define CC_ 32
#define HH 128
#define WW 128
#define FF 64
#define ORR 64
#define OCC 64

#define XS_STRIDE 36
#define WS_STRIDE 68
#define XS_BUF (2*32*XS_STRIDE)            // floats per buffer
#define WS_BUF (2*32*WS_STRIDE)
#define SMEM_BYTES ((2*XS_BUF + 2*WS_BUF) * 4)   // 53248 B

__device__ __forceinline__ void fma2(unsigned long long& d,
                                     unsigned long long a,
                                     unsigned long long b) {
    asm("fma.rn.f32x2 %0, %1, %2, %3;" : "=l"(d) : "l"(a), "l"(b), "l"(d));
}
__device__ __forceinline__ unsigned long long bcast2(float v) {
    unsigned long long r;
    unsigned int u = __float_as_uint(v);
    asm("mov.b64 %0, {%1, %1};" : "=l"(r) : "r"(u));
    return r;
}

__global__ __launch_bounds__(512, 1)
void lc2d_kernel(const float* __restrict__ x,
                 const float* __restrict__ w,
                 const float* __restrict__ bias,
                 float* __restrict__ out) {
    extern __shared__ float smem[];
    float* xs = smem;                // [buf][cc][px(32)][36]
    float* ws = smem + 2 * XS_BUF;   // [buf][cc][px(32)][68]

    const int tid  = threadIdx.x;
    const int or_  = blockIdx.y;          // pooled row
    const int oct0 = blockIdx.x * 8;      // pooled col base
    const int h0   = or_ * 2;
    const int w0   = oct0 * 2;

    // compute-side mapping
    const int g    = tid >> 6;            // pooled col within tile
    const int r    = tid & 63;
    const int bsub = r & 7;
    const int fsub = r >> 3;

    // loader-side mapping
    const int xcol = tid & 15;
    const int xb   = (tid >> 4) & 31;
    const int wsv  = tid & 7;
    const int wf   = tid >> 3;

    const float* xg = x + ((size_t)xb * CC_ * HH + h0) * WW + w0 + xcol;
    const float* wg = w + ((size_t)wf * CC_ * HH + h0) * WW + w0 + 2 * wsv;

    unsigned long long acc[4][4];
#pragma unroll
    for (int i = 0; i < 4; ++i)
#pragma unroll
        for (int j = 0; j < 4; ++j) acc[i][j] = 0ull;

    float  px_[4];
    float2 pw_[4];

    // ---- prefetch + stage 0 store ----
#pragma unroll
    for (int cc = 0; cc < 2; ++cc)
#pragma unroll
        for (int rr = 0; rr < 2; ++rr) {
            px_[cc * 2 + rr] = xg[((size_t)cc * HH + rr) * WW];
            pw_[cc * 2 + rr] = *(const float2*)&wg[((size_t)cc * HH + rr) * WW];
        }
#pragma unroll
    for (int cc = 0; cc < 2; ++cc)
#pragma unroll
        for (int rr = 0; rr < 2; ++rr) {
            xs[(cc * 32 + rr * 16 + xcol) * XS_STRIDE + xb] = px_[cc * 2 + rr];
            const float2 v = pw_[cc * 2 + rr];
            ws[(cc * 32 + rr * 16 + 2 * wsv)     * WS_STRIDE + wf] = v.x;
            ws[(cc * 32 + rr * 16 + 2 * wsv + 1) * WS_STRIDE + wf] = v.y;
        }
    __syncthreads();

    for (int s = 0; s < 16; ++s) {
        const int cur = s & 1;

        // ---- prefetch stage s+1 (global) ----
        if (s + 1 < 16) {
            const int cn = (s + 1) * 2;
#pragma unroll
            for (int cc = 0; cc < 2; ++cc)
#pragma unroll
                for (int rr = 0; rr < 2; ++rr) {
                    px_[cc * 2 + rr] = xg[((size_t)(cn + cc) * HH + rr) * WW];
                    pw_[cc * 2 + rr] = *(const float2*)&wg[((size_t)(cn + cc) * HH + rr) * WW];
                }
        }

        // ---- compute on buffer cur ----
        const float* xsb = xs + cur * XS_BUF;
        const float* wsb = ws + cur * WS_BUF;
#pragma unroll
        for (int cc = 0; cc < 2; ++cc) {
#pragma unroll
            for (int pp = 0; pp < 4; ++pp) {
                const int px = 2 * g + (pp & 1) + ((pp >> 1) ? 16 : 0);
                const float4 xa =
                    *(const float4*)&xsb[(cc * 32 + px) * XS_STRIDE + bsub * 4];
                const ulonglong2 wq0 =
                    *(const ulonglong2*)&wsb[(cc * 32 + px) * WS_STRIDE + fsub * 8];
                const ulonglong2 wq1 =
                    *(const ulonglong2*)&wsb[(cc * 32 + px) * WS_STRIDE + fsub * 8 + 4];
                const float xv[4] = {xa.x, xa.y, xa.z, xa.w};
#pragma unroll
                for (int bi = 0; bi < 4; ++bi) {
                    const unsigned long long xb2 = bcast2(xv[bi]);
                    fma2(acc[bi][0], xb2, wq0.x);
                    fma2(acc[bi][1], xb2, wq0.y);
                    fma2(acc[bi][2], xb2, wq1.x);
                    fma2(acc[bi][3], xb2, wq1.y);
                }
            }
        }

        // ---- store prefetched stage into the other buffer ----
        if (s + 1 < 16) {
            const int nxt = cur ^ 1;
            float* xsn = xs + nxt * XS_BUF;
            float* wsn = ws + nxt * WS_BUF;
#pragma unroll
            for (int cc = 0; cc < 2; ++cc)
#pragma unroll
                for (int rr = 0; rr < 2; ++rr) {
                    xsn[(cc * 32 + rr * 16 + xcol) * XS_STRIDE + xb] = px_[cc * 2 + rr];
                    const float2 v = pw_[cc * 2 + rr];
                    wsn[(cc * 32 + rr * 16 + 2 * wsv)     * WS_STRIDE + wf] = v.x;
                    wsn[(cc * 32 + rr * 16 + 2 * wsv + 1) * WS_STRIDE + wf] = v.y;
                }
        }
        __syncthreads();
    }

    // ---- epilogue: bias (raw keras reshape) + relu + store ----
    const int oc = oct0 + g;
#pragma unroll
    for (int bi = 0; bi < 4; ++bi) {
        const int b_ = bsub * 4 + bi;
#pragma unroll
        for (int j = 0; j < 4; ++j) {
            const int f0 = fsub * 8 + 2 * j;
            unsigned int lo, hi;
            asm("mov.b64 {%0, %1}, %2;" : "=r"(lo), "=r"(hi) : "l"(acc[bi][j]));
            const float bv0 = bias[(size_t)f0 * ORR * OCC + or_ * OCC + oc];
            const float bv1 = bias[(size_t)(f0 + 1) * ORR * OCC + or_ * OCC + oc];
            const float v0 = __uint_as_float(lo) + bv0;
            const float v1 = __uint_as_float(hi) + bv1;
            out[(((size_t)b_ * FF + f0)     * ORR + or_) * OCC + oc] = fmaxf(v0, 0.f);
            out[(((size_t)b_ * FF + f0 + 1) * ORR + or_) * OCC + oc] = fmaxf(v1, 0.f);
        }
    }
}

extern "C" void kernel_launch(void* const* d_in, const int* in_sizes, int n_in,
                              void* d_out, int out_size) {
    const float* x    = (const float*)d_in[0];
    const float* w    = (const float*)d_in[1];
    const float* bias = (const float*)d_in[2];
    float* out        = (float*)d_out;

    cudaFuncSetAttribute(lc2d_kernel,
                         cudaFuncAttributeMaxDynamicSharedMemorySize, SMEM_BYTES);

    dim3 grid(OCC / 8, ORR, 1);
    lc2d_kernel<<<grid, 512, SMEM_BYTES>>>(x, w, bias, out);
}

// round 3
// speedup vs baseline: 1.3649x; 1.1169x over previous
#include <cuda_runtime.h>

#define CC_ 32
#define HH 128
#define WW 128
#define FF 64
#define ORR 64
#define OCC 64

#define PX 16                         // 2 rows x 8 input cols per tile
#define XS_STRIDE 36
#define WS_STRIDE 68
#define XS_BUF (4*PX*XS_STRIDE)       // floats per buffer (4 channels/stage)
#define WS_BUF (4*PX*WS_STRIDE)
#define SMEM_BYTES ((2*XS_BUF + 2*WS_BUF) * 4)   // 53248 B

__device__ __forceinline__ void fma2(unsigned long long& d,
                                     unsigned long long a,
                                     unsigned long long b) {
    asm("fma.rn.f32x2 %0, %1, %2, %3;" : "=l"(d) : "l"(a), "l"(b), "l"(d));
}
__device__ __forceinline__ unsigned long long bcast2(float v) {
    unsigned long long r;
    unsigned int u = __float_as_uint(v);
    asm("mov.b64 %0, {%1, %1};" : "=l"(r) : "r"(u));
    return r;
}

__global__ __launch_bounds__(256, 2)
void lc2d_kernel(const float* __restrict__ x,
                 const float* __restrict__ w,
                 const float* __restrict__ bias,
                 float* __restrict__ out) {
    extern __shared__ float smem[];
    float* xs = smem;                // [buf][cc4][px16][36]
    float* ws = smem + 2 * XS_BUF;   // [buf][cc4][px16][68]

    const int tid  = threadIdx.x;
    const int or_  = blockIdx.y;          // pooled row
    const int oct0 = blockIdx.x * 4;      // pooled col base (4 per CTA)
    const int h0   = or_ * 2;
    const int w0   = oct0 * 2;

    // compute-side mapping: g = pooled col (0..3), per-warp constant
    const int g    = tid >> 6;
    const int r    = tid & 63;
    const int bsub = r & 7;
    const int fsub = r >> 3;

    // loader-side mapping
    const int xcol = tid & 7;             // 0..7 input col
    const int xb   = tid >> 3;            // 0..31 batch
    const int wsv  = tid & 3;             // col pair (2 floats), 0..3
    const int wf   = tid >> 2;            // 0..63 filter

    const float* xg = x + ((size_t)xb * CC_ * HH + h0) * WW + w0 + xcol;
    const float* wg = w + ((size_t)wf * CC_ * HH + h0) * WW + w0 + 2 * wsv;

    unsigned long long acc[4][4];
#pragma unroll
    for (int i = 0; i < 4; ++i)
#pragma unroll
        for (int j = 0; j < 4; ++j) acc[i][j] = 0ull;

    float  px_[8];   // [cc*2+rr]
    float2 pw_[8];

    // ---- prologue: prefetch stage 0 (c=0..3) and store to buffer 0 ----
#pragma unroll
    for (int cc = 0; cc < 4; ++cc)
#pragma unroll
        for (int rr = 0; rr < 2; ++rr) {
            px_[cc * 2 + rr] = xg[((size_t)cc * HH + rr) * WW];
            pw_[cc * 2 + rr] = *(const float2*)&wg[((size_t)cc * HH + rr) * WW];
        }
#pragma unroll
    for (int cc = 0; cc < 4; ++cc)
#pragma unroll
        for (int rr = 0; rr < 2; ++rr) {
            xs[(cc * PX + rr * 8 + xcol) * XS_STRIDE + xb] = px_[cc * 2 + rr];
            const float2 v = pw_[cc * 2 + rr];
            ws[(cc * PX + rr * 8 + 2 * wsv)     * WS_STRIDE + wf] = v.x;
            ws[(cc * PX + rr * 8 + 2 * wsv + 1) * WS_STRIDE + wf] = v.y;
        }
    __syncthreads();

    for (int s = 0; s < 8; ++s) {
        const int cur = s & 1;

        // ---- prefetch stage s+1 from global ----
        if (s + 1 < 8) {
            const int cn = (s + 1) * 4;
#pragma unroll
            for (int cc = 0; cc < 4; ++cc)
#pragma unroll
                for (int rr = 0; rr < 2; ++rr) {
                    px_[cc * 2 + rr] = xg[((size_t)(cn + cc) * HH + rr) * WW];
                    pw_[cc * 2 + rr] = *(const float2*)&wg[((size_t)(cn + cc) * HH + rr) * WW];
                }
        }

        // ---- compute on buffer cur: 4 channels x 4 pixels ----
        const float* xsb = xs + cur * XS_BUF;
        const float* wsb = ws + cur * WS_BUF;
#pragma unroll
        for (int cc = 0; cc < 4; ++cc) {
#pragma unroll
            for (int pp = 0; pp < 4; ++pp) {
                const int px = (pp >> 1) * 8 + 2 * g + (pp & 1);
                const float4 xa =
                    *(const float4*)&xsb[(cc * PX + px) * XS_STRIDE + bsub * 4];
                const ulonglong2 wq0 =
                    *(const ulonglong2*)&wsb[(cc * PX + px) * WS_STRIDE + fsub * 8];
                const ulonglong2 wq1 =
                    *(const ulonglong2*)&wsb[(cc * PX + px) * WS_STRIDE + fsub * 8 + 4];
                const float xv[4] = {xa.x, xa.y, xa.z, xa.w};
#pragma unroll
                for (int bi = 0; bi < 4; ++bi) {
                    const unsigned long long xb2 = bcast2(xv[bi]);
                    fma2(acc[bi][0], xb2, wq0.x);
                    fma2(acc[bi][1], xb2, wq0.y);
                    fma2(acc[bi][2], xb2, wq1.x);
                    fma2(acc[bi][3], xb2, wq1.y);
                }
            }
        }

        // ---- store prefetched stage into the other buffer ----
        if (s + 1 < 8) {
            const int nxt = cur ^ 1;
            float* xsn = xs + nxt * XS_BUF;
            float* wsn = ws + nxt * WS_BUF;
#pragma unroll
            for (int cc = 0; cc < 4; ++cc)
#pragma unroll
                for (int rr = 0; rr < 2; ++rr) {
                    xsn[(cc * PX + rr * 8 + xcol) * XS_STRIDE + xb] = px_[cc * 2 + rr];
                    const float2 v = pw_[cc * 2 + rr];
                    wsn[(cc * PX + rr * 8 + 2 * wsv)     * WS_STRIDE + wf] = v.x;
                    wsn[(cc * PX + rr * 8 + 2 * wsv + 1) * WS_STRIDE + wf] = v.y;
                }
        }
        __syncthreads();
    }

    // ---- epilogue: bias (raw keras reshape) + relu + store ----
    const int oc = oct0 + g;
    const float* bp = bias + (size_t)or_ * OCC + oc;
#pragma unroll
    for (int bi = 0; bi < 4; ++bi) {
        const int b_ = bsub * 4 + bi;
#pragma unroll
        for (int j = 0; j < 4; ++j) {
            const int f0 = fsub * 8 + 2 * j;
            unsigned int lo, hi;
            asm("mov.b64 {%0, %1}, %2;" : "=r"(lo), "=r"(hi) : "l"(acc[bi][j]));
            const float bv0 = bp[(size_t)f0 * ORR * OCC];
            const float bv1 = bp[(size_t)(f0 + 1) * ORR * OCC];
            const float v0 = __uint_as_float(lo) + bv0;
            const float v1 = __uint_as_float(hi) + bv1;
            out[(((size_t)b_ * FF + f0)     * ORR + or_) * OCC + oc] = fmaxf(v0, 0.f);
            out[(((size_t)b_ * FF + f0 + 1) * ORR + or_) * OCC + oc] = fmaxf(v1, 0.f);
        }
    }
}

extern "C" void kernel_launch(void* const* d_in, const int* in_sizes, int n_in,
                              void* d_out, int out_size) {
    const float* x    = (const float*)d_in[0];
    const float* w    = (const float*)d_in[1];
    const float* bias = (const float*)d_in[2];
    float* out        = (float*)d_out;

    cudaFuncSetAttribute(lc2d_kernel,
                         cudaFuncAttributeMaxDynamicSharedMemorySize, SMEM_BYTES);

    dim3 grid(OCC / 4, ORR, 1);
    lc2d_kernel<<<grid, 256, SMEM_BYTES>>>(x, w, bias, out);
}